// round 6
// baseline (speedup 1.0000x reference)
#include <cuda_runtime.h>
#include <cuda_bf16.h>

// out[i,j] = log1p(max(0, Gauss9 ⊛ T)),  T[i,j] = Resize2x(img)[N-1-j, i] + 0.01*noise[i,j]
// Resize2x = jax.image.resize 'linear' (half-pixel centers, 2x => weights {0.25,0.75}, edge clamp)
// Blur: separable 9-tap sigma=1 Gaussian, numpy 'symmetric' padding on T.

#define NN 4096
#define MM 2048
#define TI 64
#define TJ 64
#define HALO 4
#define LI (TI + 2*HALO)   // 72
#define LJ (TJ + 2*HALO)   // 72
#define P1 73              // s1 pitch (odd -> conflict-free column access)
#define P2 76              // s2 pitch (mult of 4 -> aligned float4 loads)

__device__ __forceinline__ int symidx(int p) {
    p = (p < 0) ? (-1 - p) : p;
    return (p >= NN) ? (2 * NN - 1 - p) : p;
}

__global__ __launch_bounds__(256)
void fused_aug_kernel(const float* __restrict__ img,
                      const float* __restrict__ noise,
                      float* __restrict__ out)
{
    __shared__ float s1[LI * P1];                 // T tile + halo
    __shared__ __align__(16) float s2[TI * P2];   // vertically blurred

    const float KW[9] = {1.3383062e-4f, 4.4318616e-3f, 5.3991124e-2f,
                         2.4197145e-1f, 3.9894347e-1f, 2.4197145e-1f,
                         5.3991124e-2f, 4.4318616e-3f, 1.3383062e-4f};

    const int t    = threadIdx.x;
    const int warp = t >> 5;
    const int lane = t & 31;
    const int i0 = (int)blockIdx.y * TI - HALO;
    const int j0 = (int)blockIdx.x * TJ - HALO;

    // ---- Phase 1: noise (coalesced along j). warp -> row, lanes -> cols ----
    #pragma unroll
    for (int k = 0; k < 9; k++) {               // 72 rows / 8 warps
        int r  = warp + k * 8;
        int gi = symidx(i0 + r);
        const float* nrow = noise + (size_t)gi * NN;
        float* srow = s1 + r * P1;
        #pragma unroll
        for (int q = 0; q < 3; q++) {
            int c = lane + q * 32;
            if (c < LJ) {
                int gj = symidx(j0 + c);
                srow[c] = 0.01f * __ldg(&nrow[gj]);
            }
        }
    }
    __syncthreads();

    // ---- Phase 2: rotated 2x-resize of img (coalesced along i). warp -> col ----
    #pragma unroll
    for (int k = 0; k < 9; k++) {               // 72 cols / 8 warps
        int c = warp + k * 8;
        int a = NN - 1 - symidx(j0 + c);        // resize row coord (const per col)
        int yf = (a - 1) >> 1;                  // floor(0.5*a - 0.25)
        int y0 = max(yf, 0);
        int y1 = min(yf + 1, MM - 1);
        float fy = (a & 1) ? 0.25f : 0.75f;
        const float* r0 = img + (size_t)y0 * MM;
        const float* r1 = img + (size_t)y1 * MM;
        float* scol = s1 + c;
        #pragma unroll
        for (int q = 0; q < 3; q++) {
            int rr = lane + q * 32;
            if (rr < LI) {
                int b  = symidx(i0 + rr);       // resize col coord
                int xf = (b - 1) >> 1;
                int x0 = max(xf, 0);
                int x1 = min(xf + 1, MM - 1);
                float fx = (b & 1) ? 0.25f : 0.75f;
                float v0 = __ldg(&r0[x0]);
                float v1 = __ldg(&r0[x1]);
                float w0 = __ldg(&r1[x0]);
                float w1 = __ldg(&r1[x1]);
                float h0 = fmaf(fx, v1 - v0, v0);
                float h1 = fmaf(fx, w1 - w0, w0);
                scol[rr * P1] += fmaf(fy, h1 - h0, h0);
            }
        }
    }
    __syncthreads();

    // ---- Phase 3: vertical blur, 4 rows per task via register window ----
    #pragma unroll
    for (int k = 0; k < 2; k++) {               // 16 row-groups / 8 warps
        int ii = (warp + k * 8) * 4;
        #pragma unroll
        for (int q = 0; q < 3; q++) {
            int c = lane + q * 32;
            if (c < LJ) {
                float v[12];
                #pragma unroll
                for (int r = 0; r < 12; r++) v[r] = s1[(ii + r) * P1 + c];
                #pragma unroll
                for (int r = 0; r < 4; r++) {
                    float acc = 0.0f;
                    #pragma unroll
                    for (int d = 0; d < 9; d++) acc = fmaf(KW[d], v[r + d], acc);
                    s2[(ii + r) * P2 + c] = acc;
                }
            }
        }
    }
    __syncthreads();

    // ---- Phase 4: horizontal blur + clip + log1p, float4 stores ----
    const int oi0 = (int)blockIdx.y * TI;
    const int oj0 = (int)blockIdx.x * TJ;
    #pragma unroll
    for (int k = 0; k < 4; k++) {               // 1024 tasks / 256 threads
        int idx = t + k * 256;
        int ii = idx >> 4;
        int jj = (idx & 15) * 4;
        const float* row = &s2[ii * P2 + jj];
        float4 a0 = *(const float4*)(row);
        float4 a1 = *(const float4*)(row + 4);
        float4 a2 = *(const float4*)(row + 8);
        float v[12] = {a0.x, a0.y, a0.z, a0.w,
                       a1.x, a1.y, a1.z, a1.w,
                       a2.x, a2.y, a2.z, a2.w};
        float4 o;
        float* op = (float*)&o;
        #pragma unroll
        for (int r = 0; r < 4; r++) {
            float acc = 0.0f;
            #pragma unroll
            for (int d = 0; d < 9; d++) acc = fmaf(KW[d], v[r + d], acc);
            op[r] = log1pf(fmaxf(acc, 0.0f));
        }
        *(float4*)&out[(size_t)(oi0 + ii) * NN + (oj0 + jj)] = o;
    }
}

extern "C" void kernel_launch(void* const* d_in, const int* in_sizes, int n_in,
                              void* d_out, int out_size) {
    const float* img   = (const float*)d_in[0];   // (1,2048,2048) f32
    const float* noise = (const float*)d_in[1];   // (1,4096,4096) f32
    if (n_in >= 2 && in_sizes[0] > in_sizes[1]) {
        const float* tmp = img; img = noise; noise = tmp;
    }
    dim3 grid(NN / TJ, NN / TI);
    fused_aug_kernel<<<grid, 256>>>(img, noise, (float*)d_out);
}

// round 9
// speedup vs baseline: 1.4843x; 1.4843x over previous
#include <cuda_runtime.h>
#include <cuda_bf16.h>

// out[i,j] = log1p(max(0, Gauss9 ⊛ T)),  T[i,j] = Resize2x(img)[N-1-j, i] + 0.01*noise[i,j]
// Resize2x = jax.image.resize 'linear' (half-pixel centers, 2x => weights {0.25,0.75}, edge clamp)
// Blur: separable 9-tap sigma=1 Gaussian, numpy 'symmetric' padding on T.

#define NN 4096
#define MM 2048
#define TI 64
#define TJ 64
#define HALO 4
#define LI (TI + 2*HALO)   // 72
#define LJ (TJ + 2*HALO)   // 72
#define P1 73              // s1 pitch (odd -> conflict-free column access)
#define P2 76              // s2 pitch (mult of 4 -> aligned float4 loads)

__device__ __forceinline__ int symidx(int p) {
    p = (p < 0) ? (-1 - p) : p;
    return (p >= NN) ? (2 * NN - 1 - p) : p;
}

__global__ __launch_bounds__(256, 5)
void fused_aug_kernel(const float* __restrict__ img,
                      const float* __restrict__ noise,
                      float* __restrict__ out)
{
    __shared__ float s1[LI * P1];                 // T tile + halo
    __shared__ __align__(16) float s2[TI * P2];   // vertically blurred

    const float KW[9] = {1.3383062e-4f, 4.4318616e-3f, 5.3991124e-2f,
                         2.4197145e-1f, 3.9894347e-1f, 2.4197145e-1f,
                         5.3991124e-2f, 4.4318616e-3f, 1.3383062e-4f};

    const int t  = threadIdx.x;
    const int bx = (int)blockIdx.x;
    const int by = (int)blockIdx.y;
    const int i0 = by * TI - HALO;
    const int j0 = bx * TJ - HALO;
    const bool edge = (bx == 0) | (by == 0) | (bx == 63) | (by == 63);

    // ---- Phase A: rotated 2x-resize of img -> s1 (pure stores) ----
    if (!edge) {
        // Interior: no symidx, no clamps. Pair even/odd ii sharing 3 x-samples.
        // b = i0+ii (i0 even). even b=2k: 0.25*I[k-1]+0.75*I[k]; odd: 0.75*I[k]+0.25*I[k+1].
        #pragma unroll 3
        for (int idx = t; idx < LJ * (LI / 2); idx += 256) {
            int jj = idx / (LI / 2);
            int m  = idx - jj * (LI / 2);
            int ii = 2 * m;
            int a  = NN - 1 - (j0 + jj);          // resize row coord (per column)
            int y0 = (a - 1) >> 1;                // floor(0.5a - 0.25)
            float fy = (a & 1) ? 0.25f : 0.75f;
            const float* r0 = img + (size_t)y0 * MM;
            const float* r1 = r0 + MM;
            int k = (i0 + ii) >> 1;
            float A0 = __ldg(&r0[k - 1]);
            float A1 = __ldg(&r0[k]);
            float A2 = __ldg(&r0[k + 1]);
            float B0 = __ldg(&r1[k - 1]);
            float B1 = __ldg(&r1[k]);
            float B2 = __ldg(&r1[k + 1]);
            float e0 = fmaf(0.25f, A0, 0.75f * A1);
            float o0 = fmaf(0.75f, A1, 0.25f * A2);
            float e1 = fmaf(0.25f, B0, 0.75f * B1);
            float o1 = fmaf(0.75f, B1, 0.25f * B2);
            s1[ii * P1 + jj]       = fmaf(fy, e1 - e0, e0);
            s1[(ii + 1) * P1 + jj] = fmaf(fy, o1 - o0, o0);
        }
    } else {
        // Edge: unpaired, symidx + clamps, parity weights.
        #pragma unroll 3
        for (int idx = t; idx < LI * LJ; idx += 256) {
            int jj = idx / LI;
            int ii = idx - jj * LI;
            int a  = NN - 1 - symidx(j0 + jj);
            int b  = symidx(i0 + ii);
            int yf = (a - 1) >> 1;
            int xf = (b - 1) >> 1;
            int y0 = max(yf, 0), y1 = min(yf + 1, MM - 1);
            int x0 = max(xf, 0), x1 = min(xf + 1, MM - 1);
            float fy = (a & 1) ? 0.25f : 0.75f;
            float fx = (b & 1) ? 0.25f : 0.75f;
            const float* r0 = img + (size_t)y0 * MM;
            const float* r1 = img + (size_t)y1 * MM;
            float v0 = __ldg(&r0[x0]);
            float v1 = __ldg(&r0[x1]);
            float w0 = __ldg(&r1[x0]);
            float w1 = __ldg(&r1[x1]);
            float h0 = fmaf(fx, v1 - v0, v0);
            float h1 = fmaf(fx, w1 - w0, w0);
            s1[ii * P1 + jj] = fmaf(fy, h1 - h0, h0);
        }
    }
    __syncthreads();

    // ---- Phase B: add noise (row-major: coalesced LDG, conflict-free smem RMW) ----
    if (!edge) {
        #pragma unroll 3
        for (int idx = t; idx < LI * LJ; idx += 256) {
            int ii = idx / LJ;
            int jj = idx - ii * LJ;
            s1[ii * P1 + jj] += 0.01f * __ldg(&noise[(size_t)(i0 + ii) * NN + (j0 + jj)]);
        }
    } else {
        #pragma unroll 3
        for (int idx = t; idx < LI * LJ; idx += 256) {
            int ii = idx / LJ;
            int jj = idx - ii * LJ;
            int gi = symidx(i0 + ii);
            int gj = symidx(j0 + jj);
            s1[ii * P1 + jj] += 0.01f * __ldg(&noise[(size_t)gi * NN + gj]);
        }
    }
    __syncthreads();

    // ---- Phase C: vertical 9-tap blur, 4 rows per task via register window ----
    for (int idx = t; idx < (TI / 4) * LJ; idx += 256) {
        int ib = idx / LJ;                   // 0..15
        int jj = idx - ib * LJ;
        int ii = ib * 4;
        float v[12];
        #pragma unroll
        for (int r = 0; r < 12; r++) v[r] = s1[(ii + r) * P1 + jj];
        #pragma unroll
        for (int r = 0; r < 4; r++) {
            float acc = 0.0f;
            #pragma unroll
            for (int d = 0; d < 9; d++) acc = fmaf(KW[d], v[r + d], acc);
            s2[(ii + r) * P2 + jj] = acc;
        }
    }
    __syncthreads();

    // ---- Phase D: horizontal blur + clip + log1p, float4 stores ----
    const int oi0 = by * TI;
    const int oj0 = bx * TJ;
    #pragma unroll
    for (int k = 0; k < 4; k++) {
        int idx = t + k * 256;
        int ii = idx >> 4;
        int jj = (idx & 15) * 4;
        const float* row = &s2[ii * P2 + jj];
        float4 a0 = *(const float4*)(row);
        float4 a1 = *(const float4*)(row + 4);
        float4 a2 = *(const float4*)(row + 8);
        float v[12] = {a0.x, a0.y, a0.z, a0.w,
                       a1.x, a1.y, a1.z, a1.w,
                       a2.x, a2.y, a2.z, a2.w};
        float4 o;
        float* op = (float*)&o;
        #pragma unroll
        for (int r = 0; r < 4; r++) {
            float acc = 0.0f;
            #pragma unroll
            for (int d = 0; d < 9; d++) acc = fmaf(KW[d], v[r + d], acc);
            op[r] = log1pf(fmaxf(acc, 0.0f));
        }
        *(float4*)&out[(size_t)(oi0 + ii) * NN + (oj0 + jj)] = o;
    }
}

extern "C" void kernel_launch(void* const* d_in, const int* in_sizes, int n_in,
                              void* d_out, int out_size) {
    const float* img   = (const float*)d_in[0];   // (1,2048,2048) f32
    const float* noise = (const float*)d_in[1];   // (1,4096,4096) f32
    if (n_in >= 2 && in_sizes[0] > in_sizes[1]) {
        const float* tmp = img; img = noise; noise = tmp;
    }
    dim3 grid(NN / TJ, NN / TI);
    fused_aug_kernel<<<grid, 256>>>(img, noise, (float*)d_out);
}

// round 10
// speedup vs baseline: 1.8361x; 1.2370x over previous
#include <cuda_runtime.h>
#include <cuda_bf16.h>

// out[i,j] = log1p(max(0, Gauss9 ⊛ T)),  T[i,j] = Resize2x(img)[N-1-j, i] + 0.01*noise[i,j]
// Resize2x = jax.image.resize 'linear' (half-pixel centers, 2x => weights {0.25,0.75}, edge clamp)
// Blur: separable 9-tap sigma=1 Gaussian, numpy 'symmetric' padding on T.

#define NN 4096
#define MM 2048
#define TI 64
#define TJ 64
#define HALO 4
#define LI (TI + 2*HALO)   // 72
#define LJ (TJ + 2*HALO)   // 72
#define P1 73              // s1 pitch (odd -> conflict-free column access)
#define P2 76              // s2 pitch (mult of 4 -> aligned float4 loads)

__device__ __forceinline__ int symidx(int p) {
    p = (p < 0) ? (-1 - p) : p;
    return (p >= NN) ? (2 * NN - 1 - p) : p;
}

__global__ __launch_bounds__(256, 5)
void fused_aug_kernel(const float* __restrict__ img,
                      const float* __restrict__ noise,
                      float* __restrict__ out)
{
    __shared__ float s1[LI * P1];                 // T tile + halo (img part for interior)
    __shared__ __align__(16) float s2[TI * P2];   // vertically blurred

    const float KW[9] = {1.3383062e-4f, 4.4318616e-3f, 5.3991124e-2f,
                         2.4197145e-1f, 3.9894347e-1f, 2.4197145e-1f,
                         5.3991124e-2f, 4.4318616e-3f, 1.3383062e-4f};

    const int t  = threadIdx.x;
    const int bx = (int)blockIdx.x;
    const int by = (int)blockIdx.y;
    const int i0 = by * TI - HALO;
    const int j0 = bx * TJ - HALO;
    const bool edge = (bx == 0) | (by == 0) | (bx == 63) | (by == 63);

    if (!edge) {
        // ---- Phase A (interior): rotated 2x-resize, 2x2 outputs/thread ----
        // jj odd  -> a = 4095-(j0+jj) even = 2p  : rows (p-1,p) w (0.25,0.75)
        // jj even -> a odd                        : same rows  w (0.75,0.25)
        // Pair (jj,jj+1) with jj odd shares rows; ii pair (2m,2m+1) shares cols k-1,k,k+1.
        for (int idx = t; idx < 35 * 36; idx += 256) {
            int c  = idx / 36;
            int m  = idx - c * 36;
            int jj = 2 * c + 1;
            int ii = 2 * m;
            int a  = 4095 - (j0 + jj);            // even
            int p  = a >> 1;
            const float* r0 = img + (size_t)(p - 1) * MM;
            const float* r1 = r0 + MM;
            int k = (i0 + ii) >> 1;
            float A0 = __ldg(&r0[k - 1]);
            float A1 = __ldg(&r0[k]);
            float A2 = __ldg(&r0[k + 1]);
            float B0 = __ldg(&r1[k - 1]);
            float B1 = __ldg(&r1[k]);
            float B2 = __ldg(&r1[k + 1]);
            float ea = fmaf(0.25f, A0, 0.75f * A1);   // row p-1, even b
            float oa = fmaf(0.75f, A1, 0.25f * A2);   // row p-1, odd b
            float eb = fmaf(0.25f, B0, 0.75f * B1);   // row p,   even b
            float ob = fmaf(0.75f, B1, 0.25f * B2);   // row p,   odd b
            float* s = s1 + ii * P1 + jj;
            s[0]      = fmaf(0.25f, ea, 0.75f * eb);  // (ii, jj)
            s[1]      = fmaf(0.75f, ea, 0.25f * eb);  // (ii, jj+1)
            s[P1]     = fmaf(0.25f, oa, 0.75f * ob);  // (ii+1, jj)
            s[P1 + 1] = fmaf(0.75f, oa, 0.25f * ob);  // (ii+1, jj+1)
        }
        // Leftover columns jj = 0 and jj = 71 (36 ii-pairs each)
        if (t < 72) {
            int col = t / 36;
            int m   = t - col * 36;
            int jj  = col ? (LJ - 1) : 0;
            int ii  = 2 * m;
            int a   = 4095 - (j0 + jj);
            int yf  = (a - 1) >> 1;
            float fy = (a & 1) ? 0.25f : 0.75f;
            const float* r0 = img + (size_t)yf * MM;
            const float* r1 = r0 + MM;
            int k = (i0 + ii) >> 1;
            float A0 = __ldg(&r0[k - 1]);
            float A1 = __ldg(&r0[k]);
            float A2 = __ldg(&r0[k + 1]);
            float B0 = __ldg(&r1[k - 1]);
            float B1 = __ldg(&r1[k]);
            float B2 = __ldg(&r1[k + 1]);
            float ea = fmaf(0.25f, A0, 0.75f * A1);
            float oa = fmaf(0.75f, A1, 0.25f * A2);
            float eb = fmaf(0.25f, B0, 0.75f * B1);
            float ob = fmaf(0.75f, B1, 0.25f * B2);
            s1[ii * P1 + jj]       = fmaf(fy, eb - ea, ea);
            s1[(ii + 1) * P1 + jj] = fmaf(fy, ob - oa, oa);
        }
        __syncthreads();

        // ---- Phase C (interior): noise fused into vertical blur, 8-row strips ----
        for (int idx = t; idx < 8 * LJ; idx += 256) {   // 576 tasks
            int g  = idx / LJ;
            int jj = idx - g * LJ;
            int ii = g * 8;
            const float* np = noise + (size_t)(i0 + ii) * NN + (j0 + jj);
            float v[16];
            #pragma unroll
            for (int r = 0; r < 16; r++)
                v[r] = fmaf(0.01f, __ldg(&np[(size_t)r * NN]), s1[(ii + r) * P1 + jj]);
            #pragma unroll
            for (int r = 0; r < 8; r++) {
                float acc = 0.0f;
                #pragma unroll
                for (int d = 0; d < 9; d++) acc = fmaf(KW[d], v[r + d], acc);
                s2[(ii + r) * P2 + jj] = acc;
            }
        }
    } else {
        // ---- Phase A (edge): symidx + clamps ----
        #pragma unroll 3
        for (int idx = t; idx < LI * LJ; idx += 256) {
            int jj = idx / LI;
            int ii = idx - jj * LI;
            int a  = NN - 1 - symidx(j0 + jj);
            int b  = symidx(i0 + ii);
            int yf = (a - 1) >> 1;
            int xf = (b - 1) >> 1;
            int y0 = max(yf, 0), y1 = min(yf + 1, MM - 1);
            int x0 = max(xf, 0), x1 = min(xf + 1, MM - 1);
            float fy = (a & 1) ? 0.25f : 0.75f;
            float fx = (b & 1) ? 0.25f : 0.75f;
            const float* r0 = img + (size_t)y0 * MM;
            const float* r1 = img + (size_t)y1 * MM;
            float v0 = __ldg(&r0[x0]);
            float v1 = __ldg(&r0[x1]);
            float w0 = __ldg(&r1[x0]);
            float w1 = __ldg(&r1[x1]);
            float h0 = fmaf(fx, v1 - v0, v0);
            float h1 = fmaf(fx, w1 - w0, w0);
            s1[ii * P1 + jj] = fmaf(fy, h1 - h0, h0);
        }
        __syncthreads();

        // ---- Phase B (edge): add noise with symidx ----
        #pragma unroll 3
        for (int idx = t; idx < LI * LJ; idx += 256) {
            int ii = idx / LJ;
            int jj = idx - ii * LJ;
            int gi = symidx(i0 + ii);
            int gj = symidx(j0 + jj);
            s1[ii * P1 + jj] += 0.01f * __ldg(&noise[(size_t)gi * NN + gj]);
        }
        __syncthreads();

        // ---- Phase C (edge): vertical blur, 8-row strips ----
        for (int idx = t; idx < 8 * LJ; idx += 256) {
            int g  = idx / LJ;
            int jj = idx - g * LJ;
            int ii = g * 8;
            float v[16];
            #pragma unroll
            for (int r = 0; r < 16; r++) v[r] = s1[(ii + r) * P1 + jj];
            #pragma unroll
            for (int r = 0; r < 8; r++) {
                float acc = 0.0f;
                #pragma unroll
                for (int d = 0; d < 9; d++) acc = fmaf(KW[d], v[r + d], acc);
                s2[(ii + r) * P2 + jj] = acc;
            }
        }
    }
    __syncthreads();

    // ---- Phase D: horizontal blur + clip + fast log1p, 8 outputs/thread ----
    const int oi0 = by * TI;
    const int oj0 = bx * TJ;
    #pragma unroll
    for (int q = 0; q < 2; q++) {                 // 512 tasks
        int idx = t + q * 256;
        int ii = idx >> 3;
        int jj = (idx & 7) * 8;
        const float* row = &s2[ii * P2 + jj];
        float4 a0 = *(const float4*)(row);
        float4 a1 = *(const float4*)(row + 4);
        float4 a2 = *(const float4*)(row + 8);
        float4 a3 = *(const float4*)(row + 12);
        float v[16] = {a0.x, a0.y, a0.z, a0.w,  a1.x, a1.y, a1.z, a1.w,
                       a2.x, a2.y, a2.z, a2.w,  a3.x, a3.y, a3.z, a3.w};
        float4 o0, o1;
        float* op = (float*)&o0;                  // o0,o1 contiguous on stack
        float res[8];
        #pragma unroll
        for (int r = 0; r < 8; r++) {
            float acc = 0.0f;
            #pragma unroll
            for (int d = 0; d < 9; d++) acc = fmaf(KW[d], v[r + d], acc);
            res[r] = __logf(1.0f + fmaxf(acc, 0.0f));
        }
        o0 = make_float4(res[0], res[1], res[2], res[3]);
        o1 = make_float4(res[4], res[5], res[6], res[7]);
        float* dst = &out[(size_t)(oi0 + ii) * NN + (oj0 + jj)];
        *(float4*)(dst)     = o0;
        *(float4*)(dst + 4) = o1;
        (void)op;
    }
}

extern "C" void kernel_launch(void* const* d_in, const int* in_sizes, int n_in,
                              void* d_out, int out_size) {
    const float* img   = (const float*)d_in[0];   // (1,2048,2048) f32
    const float* noise = (const float*)d_in[1];   // (1,4096,4096) f32
    if (n_in >= 2 && in_sizes[0] > in_sizes[1]) {
        const float* tmp = img; img = noise; noise = tmp;
    }
    dim3 grid(NN / TJ, NN / TI);
    fused_aug_kernel<<<grid, 256>>>(img, noise, (float*)d_out);
}